// round 10
// baseline (speedup 1.0000x reference)
#include <cuda_runtime.h>
#include <cuda_bf16.h>
#include <cstdint>

#define Bn 2
#define Sn 2048
#define Dn 1024
#define Hn 16
#define HDn 64
#define Mn (Bn*Sn)
#define ATT_SCALE 0.125f   /* 64^-0.5 */

// int8 digit splits for QKV GEMM
static __device__ int8_t g_xa1[(size_t)Mn*Dn], g_xa2[(size_t)Mn*Dn];
static __device__ int8_t g_wq1[(size_t)Dn*Dn], g_wq2[(size_t)Dn*Dn];
static __device__ int8_t g_wk1[(size_t)Dn*Dn], g_wk2[(size_t)Dn*Dn];
static __device__ int8_t g_wv1[(size_t)Dn*Dn], g_wv2[(size_t)Dn*Dn];
static __device__ unsigned g_scales[4];        // maxabs bits: x, wq, wk, wv
// bf16 hi/lo for attention + O-proj
static __device__ __nv_bfloat16 g_woh[(size_t)Dn*Dn], g_wol[(size_t)Dn*Dn];
static __device__ __nv_bfloat16 g_qh[(size_t)Mn*Dn],  g_ql[(size_t)Mn*Dn];
static __device__ __nv_bfloat16 g_kh[(size_t)Mn*Dn],  g_kl[(size_t)Mn*Dn];
static __device__ __nv_bfloat16 g_vh[(size_t)Mn*Dn],  g_vl[(size_t)Mn*Dn];
static __device__ __nv_bfloat16 g_aoh[(size_t)Mn*Dn], g_aol[(size_t)Mn*Dn];

// ---------------------------------------------------------------------------
// scale prep
// ---------------------------------------------------------------------------
__global__ void zero_scales(unsigned* s) { if (threadIdx.x < 4) s[threadIdx.x] = 0u; }

__global__ __launch_bounds__(256) void maxabs(const float* __restrict__ src, int n,
                                              unsigned* __restrict__ slot)
{
    float m = 0.f;
    for (int i = blockIdx.x * 256 + threadIdx.x; i < n; i += gridDim.x * 256)
        m = fmaxf(m, fabsf(src[i]));
#pragma unroll
    for (int off = 16; off; off >>= 1)
        m = fmaxf(m, __shfl_xor_sync(0xffffffffu, m, off));
    if ((threadIdx.x & 31) == 0) atomicMax(slot, __float_as_uint(m));
}

// fp32 -> int8 digits: x ~= s*(a1 + a2/128), s = max/127
__global__ __launch_bounds__(256) void split_i8(const float4* __restrict__ src,
    char4* __restrict__ a1, char4* __restrict__ a2,
    const unsigned* __restrict__ slot, int n4)
{
    int i = blockIdx.x * 256 + threadIdx.x;
    if (i >= n4) return;
    const float rs = 127.f / fmaxf(__uint_as_float(*slot), 1e-20f);
    float4 v = src[i];
    float f0 = v.x * rs, f1 = v.y * rs, f2 = v.z * rs, f3 = v.w * rs;
    int i0 = __float2int_rn(f0), i1 = __float2int_rn(f1);
    int i2 = __float2int_rn(f2), i3 = __float2int_rn(f3);
    int j0 = __float2int_rn((f0 - i0) * 128.f);
    int j1 = __float2int_rn((f1 - i1) * 128.f);
    int j2 = __float2int_rn((f2 - i2) * 128.f);
    int j3 = __float2int_rn((f3 - i3) * 128.f);
    a1[i] = make_char4((char)i0, (char)i1, (char)i2, (char)i3);
    a2[i] = make_char4((char)j0, (char)j1, (char)j2, (char)j3);
}

// fp32 -> bf16 hi/lo (for wo)
__global__ __launch_bounds__(256) void split_bf16(const float4* __restrict__ src,
    __nv_bfloat162* __restrict__ hi, __nv_bfloat162* __restrict__ lo, int n4)
{
    int i = blockIdx.x * 256 + threadIdx.x;
    if (i >= n4) return;
    float4 v = src[i];
    __nv_bfloat16 hx = __float2bfloat16_rn(v.x);
    __nv_bfloat16 hy = __float2bfloat16_rn(v.y);
    __nv_bfloat16 hz = __float2bfloat16_rn(v.z);
    __nv_bfloat16 hw = __float2bfloat16_rn(v.w);
    hi[2 * i]     = __nv_bfloat162(hx, hy);
    hi[2 * i + 1] = __nv_bfloat162(hz, hw);
    lo[2 * i]     = __nv_bfloat162(__float2bfloat16_rn(v.x - __bfloat162float(hx)),
                                   __float2bfloat16_rn(v.y - __bfloat162float(hy)));
    lo[2 * i + 1] = __nv_bfloat162(__float2bfloat16_rn(v.z - __bfloat162float(hz)),
                                   __float2bfloat16_rn(v.w - __bfloat162float(hw)));
}

// ---------------------------------------------------------------------------
// helpers
// ---------------------------------------------------------------------------
__device__ __forceinline__ uint32_t s2u(const void* p) {
    return (uint32_t)__cvta_generic_to_shared(p);
}

__device__ __forceinline__ void mma16(float* d, const uint32_t* a,
                                      uint32_t b0, uint32_t b1) {
    asm volatile(
        "mma.sync.aligned.m16n8k16.row.col.f32.bf16.bf16.f32 "
        "{%0,%1,%2,%3},{%4,%5,%6,%7},{%8,%9},{%0,%1,%2,%3};"
        : "+f"(d[0]), "+f"(d[1]), "+f"(d[2]), "+f"(d[3])
        : "r"(a[0]), "r"(a[1]), "r"(a[2]), "r"(a[3]), "r"(b0), "r"(b1));
}

__device__ __forceinline__ void imma32(int* d, const uint32_t* a,
                                       uint32_t b0, uint32_t b1) {
    asm volatile(
        "mma.sync.aligned.m16n8k32.row.col.s32.s8.s8.s32 "
        "{%0,%1,%2,%3},{%4,%5,%6,%7},{%8,%9},{%0,%1,%2,%3};"
        : "+r"(d[0]), "+r"(d[1]), "+r"(d[2]), "+r"(d[3])
        : "r"(a[0]), "r"(a[1]), "r"(a[2]), "r"(a[3]), "r"(b0), "r"(b1));
}

__device__ __forceinline__ void cp16(uint32_t s, const void* g) {
    asm volatile("cp.async.cg.shared.global [%0], [%1], 16;" :: "r"(s), "l"(g));
}

__device__ __forceinline__ void pack_hl(uint32_t& hi, uint32_t& lo, float a, float b) {
    __nv_bfloat162 h = __float22bfloat162_rn(make_float2(a, b));
    float2 hf = __bfloat1622float2(h);
    __nv_bfloat162 l = __float22bfloat162_rn(make_float2(a - hf.x, b - hf.y));
    hi = *(uint32_t*)&h; lo = *(uint32_t*)&l;
}

#define LDSM_X4(r0,r1,r2,r3, addr) \
    asm volatile("ldmatrix.sync.aligned.m8n8.x4.shared.b16 {%0,%1,%2,%3}, [%4];" \
        : "=r"(r0), "=r"(r1), "=r"(r2), "=r"(r3) : "r"(addr))

#define LDSM_X4_T(r0,r1,r2,r3, addr) \
    asm volatile("ldmatrix.sync.aligned.m8n8.x4.trans.shared.b16 {%0,%1,%2,%3}, [%4];" \
        : "=r"(r0), "=r"(r1), "=r"(r2), "=r"(r3) : "r"(addr))

// ---------------------------------------------------------------------------
// INT8 2-digit QKV GEMM: C = s*(a1b1 + (a1b2 + a2b1)/128) + bias -> bf16 h/l.
// Block 128x128, K-chunk 64 (int8), cp.async double-buffered.
// b16-view fragment addressing identical to the proven bf16 kernel.
// ---------------------------------------------------------------------------
#define IARR 10240                /* 128 rows x 80B per array per stage */

__global__ __launch_bounds__(256) void gemm_i8_qkv(
    const int8_t* __restrict__ A1, const int8_t* __restrict__ A2,
    const int8_t* __restrict__ B1q, const int8_t* __restrict__ B2q,
    const int8_t* __restrict__ B1k, const int8_t* __restrict__ B2k,
    const int8_t* __restrict__ B1v, const int8_t* __restrict__ B2v,
    const float* __restrict__ bias0, const float* __restrict__ bias1,
    const float* __restrict__ bias2,
    const unsigned* __restrict__ scales,
    __nv_bfloat16* __restrict__ Ch0, __nv_bfloat16* __restrict__ Cl0,
    __nv_bfloat16* __restrict__ Ch1, __nv_bfloat16* __restrict__ Cl1,
    __nv_bfloat16* __restrict__ Ch2, __nv_bfloat16* __restrict__ Cl2,
    int M, int N, int K)
{
    extern __shared__ char dynsmem[];

    const int wsel = blockIdx.x >> 3;
    const int8_t* B1 = (wsel == 0) ? B1q : (wsel == 1) ? B1k : B1v;
    const int8_t* B2 = (wsel == 0) ? B2q : (wsel == 1) ? B2k : B2v;
    const float* bias = (wsel == 0) ? bias0 : (wsel == 1) ? bias1 : bias2;
    __nv_bfloat16* Ch = (wsel == 0) ? Ch0 : (wsel == 1) ? Ch1 : Ch2;
    __nv_bfloat16* Cl = (wsel == 0) ? Cl0 : (wsel == 1) ? Cl1 : Cl2;

    const int m0 = blockIdx.y * 128, n0 = (blockIdx.x & 7) * 128;
    const int tid = threadIdx.x;
    const int lane = tid & 31, wid = tid >> 5;
    const int g = lane >> 2, t = lane & 3;
    const int mBase = (wid & 3) * 32;
    const int nBase = (wid >> 2) * 64;

    // loader: 2 threads/row, each 32B base + 2 x 16B chunks
    const int lrow = tid >> 1;
    const int lcb = (tid & 1) * 32;

    const uint32_t sbase = s2u(dynsmem);
    const uint32_t dA1 = sbase + (uint32_t)(lrow * 80 + lcb);
    const uint32_t dA2 = dA1 + 2 * IARR;
    const uint32_t dB1 = dA1 + 4 * IARR;
    const uint32_t dB2 = dA1 + 6 * IARR;
    const int8_t* gA1 = A1 + (size_t)(m0 + lrow) * K + lcb;
    const int8_t* gA2 = A2 + (size_t)(m0 + lrow) * K + lcb;
    const int8_t* gB1 = B1 + (size_t)(n0 + lrow) * K + lcb;
    const int8_t* gB2 = B2 + (size_t)(n0 + lrow) * K + lcb;

    // ldmatrix lane components (b16-view, identical to bf16 kernel)
    const int arow = lane & 15;
    const int acol = (lane >> 4) << 3;
    const int brow = (lane & 7) + ((lane >> 4) << 3);
    const int bcol = ((lane >> 3) & 1) << 3;

    int accm[2][8][4], accc[2][8][4];
#pragma unroll
    for (int i = 0; i < 2; i++)
#pragma unroll
        for (int j = 0; j < 8; j++)
#pragma unroll
            for (int l = 0; l < 4; l++) { accm[i][j][l] = 0; accc[i][j][l] = 0; }

    const int nCh = K / 64;   // 16

    auto issue = [&](int kt, int buf) {
        uint32_t so = (uint32_t)(buf * IARR);
#pragma unroll
        for (int c = 0; c < 2; c++) {
            cp16(dA1 + so + c * 16, gA1 + kt + c * 16);
            cp16(dA2 + so + c * 16, gA2 + kt + c * 16);
            cp16(dB1 + so + c * 16, gB1 + kt + c * 16);
            cp16(dB2 + so + c * 16, gB2 + kt + c * 16);
        }
        asm volatile("cp.async.commit_group;");
    };

    issue(0, 0);

    for (int cc = 0; cc < nCh; cc++) {
        const int buf = cc & 1;
        if (cc + 1 < nCh) {
            issue((cc + 1) * 64, buf ^ 1);
            asm volatile("cp.async.wait_group 1;");
        } else {
            asm volatile("cp.async.wait_group 0;");
        }
        __syncthreads();

        const uint32_t uA1 = sbase + (uint32_t)(buf * IARR);
        const uint32_t uA2 = uA1 + 2 * IARR;
        const uint32_t uB1 = uA1 + 4 * IARR;
        const uint32_t uB2 = uA1 + 6 * IARR;

#pragma unroll
        for (int ks = 0; ks < 2; ks++) {   // two k32 steps per 64B chunk
            uint32_t a1f[2][4], a2f[2][4];
#pragma unroll
            for (int mt = 0; mt < 2; mt++) {
                uint32_t aoff = (uint32_t)((mBase + mt * 16 + arow) * 80
                                           + (ks * 16 + acol) * 2);
                LDSM_X4(a1f[mt][0], a1f[mt][1], a1f[mt][2], a1f[mt][3], uA1 + aoff);
                LDSM_X4(a2f[mt][0], a2f[mt][1], a2f[mt][2], a2f[mt][3], uA2 + aoff);
            }
#pragma unroll
            for (int np = 0; np < 2; np++) {
                uint32_t b1[2][4], b2[2][4];
#pragma unroll
                for (int q = 0; q < 2; q++) {
                    uint32_t boff = (uint32_t)((nBase + (np * 2 + q) * 16 + brow) * 80
                                               + (ks * 16 + bcol) * 2);
                    LDSM_X4(b1[q][0], b1[q][1], b1[q][2], b1[q][3], uB1 + boff);
                    LDSM_X4(b2[q][0], b2[q][1], b2[q][2], b2[q][3], uB2 + boff);
                }
                // main: a1*b1 -> accm (8 distinct)
#pragma unroll
                for (int q = 0; q < 2; q++)
#pragma unroll
                    for (int mt = 0; mt < 2; mt++) {
                        imma32(accm[mt][4 * np + 2 * q],     a1f[mt], b1[q][0], b1[q][1]);
                        imma32(accm[mt][4 * np + 2 * q + 1], a1f[mt], b1[q][2], b1[q][3]);
                    }
                // cross: a1*b2 -> accc
#pragma unroll
                for (int q = 0; q < 2; q++)
#pragma unroll
                    for (int mt = 0; mt < 2; mt++) {
                        imma32(accc[mt][4 * np + 2 * q],     a1f[mt], b2[q][0], b2[q][1]);
                        imma32(accc[mt][4 * np + 2 * q + 1], a1f[mt], b2[q][2], b2[q][3]);
                    }
                // cross: a2*b1 -> accc (RAW distance 8)
#pragma unroll
                for (int q = 0; q < 2; q++)
#pragma unroll
                    for (int mt = 0; mt < 2; mt++) {
                        imma32(accc[mt][4 * np + 2 * q],     a2f[mt], b1[q][0], b1[q][1]);
                        imma32(accc[mt][4 * np + 2 * q + 1], a2f[mt], b1[q][2], b1[q][3]);
                    }
            }
        }
        __syncthreads();
    }

    const float s = (__uint_as_float(scales[0]) * (1.f / 127.f)) *
                    (__uint_as_float(scales[1 + wsel]) * (1.f / 127.f));

#pragma unroll
    for (int mt = 0; mt < 2; mt++) {
        int r0 = m0 + mBase + mt * 16 + g;
#pragma unroll
        for (int nt = 0; nt < 8; nt++) {
            int c = n0 + nBase + nt * 8 + 2 * t;
            float b0v = bias[c], b1v = bias[c + 1];
            float v00 = s * ((float)accm[mt][nt][0] + 0.0078125f * (float)accc[mt][nt][0]) + b0v;
            float v01 = s * ((float)accm[mt][nt][1] + 0.0078125f * (float)accc[mt][nt][1]) + b1v;
            float v10 = s * ((float)accm[mt][nt][2] + 0.0078125f * (float)accc[mt][nt][2]) + b0v;
            float v11 = s * ((float)accm[mt][nt][3] + 0.0078125f * (float)accc[mt][nt][3]) + b1v;
            uint32_t h0, l0, h1, l1;
            pack_hl(h0, l0, v00, v01);
            pack_hl(h1, l1, v10, v11);
            *(uint32_t*)&Ch[(size_t)r0 * N + c] = h0;
            *(uint32_t*)&Cl[(size_t)r0 * N + c] = l0;
            *(uint32_t*)&Ch[(size_t)(r0 + 8) * N + c] = h1;
            *(uint32_t*)&Cl[(size_t)(r0 + 8) * N + c] = l1;
        }
    }
}

// ---------------------------------------------------------------------------
// 3xBF16 GEMM for the O projection (proven R9 kernel, fp32 out path).
// ---------------------------------------------------------------------------
#define KT 32
#define PAD 40
#define STAGE (128 * PAD)

__global__ __launch_bounds__(256, 2) void gemm_bf16_o(
    const __nv_bfloat16* __restrict__ Ah, const __nv_bfloat16* __restrict__ Al,
    const __nv_bfloat16* __restrict__ Bh, const __nv_bfloat16* __restrict__ Bl,
    const float* __restrict__ bias, float* __restrict__ C,
    int M, int N, int K)
{
    extern __shared__ char dynsmem[];
    __nv_bfloat16* sm = (__nv_bfloat16*)dynsmem;
    __nv_bfloat16* sAh = sm;
    __nv_bfloat16* sAl = sm + 2 * STAGE;
    __nv_bfloat16* sBh = sm + 4 * STAGE;
    __nv_bfloat16* sBl = sm + 6 * STAGE;

    const int m0 = blockIdx.y * 128, n0 = blockIdx.x * 128;
    const int tid = threadIdx.x;
    const int lane = tid & 31, wid = tid >> 5;
    const int g = lane >> 2, t = lane & 3;
    const int mBase = (wid & 3) * 32;
    const int nBase = (wid >> 2) * 64;

    const int lrow = tid >> 1;
    const int lcol = (tid & 1) * 16;

    const uint32_t sbase = s2u(sm);
    const uint32_t dAh = sbase + (uint32_t)(lrow * PAD + lcol) * 2;
    const uint32_t dAl = dAh + 2 * STAGE * 2;
    const uint32_t dBh = dAh + 4 * STAGE * 2;
    const uint32_t dBl = dAh + 6 * STAGE * 2;
    const __nv_bfloat16* gAh = Ah + (size_t)(m0 + lrow) * K + lcol;
    const __nv_bfloat16* gAl = Al + (size_t)(m0 + lrow) * K + lcol;
    const __nv_bfloat16* gBh = Bh + (size_t)(n0 + lrow) * K + lcol;
    const __nv_bfloat16* gBl = Bl + (size_t)(n0 + lrow) * K + lcol;

    const int arow = lane & 15;
    const int acol = (lane >> 4) << 3;
    const int brow = (lane & 7) + ((lane >> 4) << 3);
    const int bcol = ((lane >> 3) & 1) << 3;

    float acc[2][8][4];
#pragma unroll
    for (int i = 0; i < 2; i++)
#pragma unroll
        for (int j = 0; j < 8; j++)
#pragma unroll
            for (int l = 0; l < 4; l++) acc[i][j][l] = 0.f;

    const int nTiles = K / KT;

    auto issue = [&](int kt, int buf) {
        uint32_t so = (uint32_t)(buf * STAGE * 2);
#pragma unroll
        for (int c = 0; c < 2; c++) {
            cp16(dAh + so + c * 16, gAh + kt + c * 8);
            cp16(dAl + so + c * 16, gAl + kt + c * 8);
            cp16(dBh + so + c * 16, gBh + kt + c * 8);
            cp16(dBl + so + c * 16, gBl + kt + c * 8);
        }
        asm volatile("cp.async.commit_group;");
    };

    issue(0, 0);

    for (int tt = 0; tt < nTiles; tt++) {
        const int buf = tt & 1;
        if (tt + 1 < nTiles) {
            issue((tt + 1) * KT, buf ^ 1);
            asm volatile("cp.async.wait_group 1;");
        } else {
            asm volatile("cp.async.wait_group 0;");
        }
        __syncthreads();

        const uint32_t uAh = s2u(sAh + buf * STAGE);
        const uint32_t uAl = s2u(sAl + buf * STAGE);
        const uint32_t uBh = s2u(sBh + buf * STAGE);
        const uint32_t uBl = s2u(sBl + buf * STAGE);

#pragma unroll
        for (int k16 = 0; k16 < KT; k16 += 16) {
            uint32_t ah[2][4], al[2][4];
#pragma unroll
            for (int mt = 0; mt < 2; mt++) {
                uint32_t aoff = (uint32_t)(((mBase + mt * 16 + arow) * PAD + k16 + acol) * 2);
                LDSM_X4(ah[mt][0], ah[mt][1], ah[mt][2], ah[mt][3], uAh + aoff);
                LDSM_X4(al[mt][0], al[mt][1], al[mt][2], al[mt][3], uAl + aoff);
            }
#pragma unroll
            for (int np = 0; np < 2; np++) {
                uint32_t bh[2][4], bl[2][4];
#pragma unroll
                for (int q = 0; q < 2; q++) {
                    uint32_t boff = (uint32_t)(((nBase + (np * 2 + q) * 16 + brow) * PAD + k16 + bcol) * 2);
                    LDSM_X4(bh[q][0], bh[q][1], bh[q][2], bh[q][3], uBh + boff);
                    LDSM_X4(bl[q][0], bl[q][1], bl[q][2], bl[q][3], uBl + boff);
                }
#pragma unroll
                for (int q = 0; q < 2; q++)
#pragma unroll
                    for (int mt = 0; mt < 2; mt++) {
                        mma16(acc[mt][4 * np + 2 * q],     ah[mt], bh[q][0], bh[q][1]);
                        mma16(acc[mt][4 * np + 2 * q + 1], ah[mt], bh[q][2], bh[q][3]);
                    }
#pragma unroll
                for (int q = 0; q < 2; q++)
#pragma unroll
                    for (int mt = 0; mt < 2; mt++) {
                        mma16(acc[mt][4 * np + 2 * q],     ah[mt], bl[q][0], bl[q][1]);
                        mma16(acc[mt][4 * np + 2 * q + 1], ah[mt], bl[q][2], bl[q][3]);
                    }
#pragma unroll
                for (int q = 0; q < 2; q++)
#pragma unroll
                    for (int mt = 0; mt < 2; mt++) {
                        mma16(acc[mt][4 * np + 2 * q],     al[mt], bh[q][0], bh[q][1]);
                        mma16(acc[mt][4 * np + 2 * q + 1], al[mt], bh[q][2], bh[q][3]);
                    }
            }
        }
        __syncthreads();
    }

#pragma unroll
    for (int mt = 0; mt < 2; mt++) {
        int r0 = m0 + mBase + mt * 16 + g;
#pragma unroll
        for (int nt = 0; nt < 8; nt++) {
            int c = n0 + nBase + nt * 8 + 2 * t;
            float b0v = bias[c], b1v = bias[c + 1];
            *(float2*)&C[(size_t)r0 * N + c] =
                make_float2(acc[mt][nt][0] + b0v, acc[mt][nt][1] + b1v);
            *(float2*)&C[(size_t)(r0 + 8) * N + c] =
                make_float2(acc[mt][nt][2] + b0v, acc[mt][nt][3] + b1v);
        }
    }
}

// ---------------------------------------------------------------------------
// Tensor-core flash attention (unchanged from R9).
// ---------------------------------------------------------------------------
#define AST 72

__global__ __launch_bounds__(128, 3) void attn_mma(
    const __nv_bfloat16* __restrict__ gqh, const __nv_bfloat16* __restrict__ gql,
    const __nv_bfloat16* __restrict__ gkh, const __nv_bfloat16* __restrict__ gkl,
    const __nv_bfloat16* __restrict__ gvh, const __nv_bfloat16* __restrict__ gvl,
    const int* __restrict__ doc,
    __nv_bfloat16* __restrict__ aoh, __nv_bfloat16* __restrict__ aol)
{
    extern __shared__ char dynsmem[];
    __nv_bfloat16* sKh = (__nv_bfloat16*)dynsmem;
    __nv_bfloat16* sKl = sKh + 64 * AST;
    __nv_bfloat16* sVh = sKl + 64 * AST;
    __nv_bfloat16* sVl = sVh + 64 * AST;
    __shared__ int qdoc[64], kdoc[64], srange[2];

    const int q0 = blockIdx.x * 64;
    const int h = blockIdx.y, b = blockIdx.z;
    const int tid = threadIdx.x;
    const int lane = tid & 31, w = tid >> 5;
    const int g = lane >> 2, t = lane & 3;
    const int wrow = w * 16;

    if (tid == 0) { srange[0] = Sn; srange[1] = 0; }
    if (tid < 64) qdoc[tid] = doc[q0 + tid];
    __syncthreads();
    const int dlo = qdoc[0], dhi = qdoc[63];
    for (int i = tid; i < Sn; i += 128) {
        int di = doc[i];
        if (di == dlo) atomicMin(&srange[0], i);
        if (di == dhi) atomicMax(&srange[1], i);
    }

    const size_t rowbase = (size_t)(b * Sn + q0) * Dn + h * HDn;
    uint32_t qfh[4][4], qfl[4][4];
    {
        const size_t r0 = rowbase + (size_t)(wrow + g) * Dn + 2 * t;
        const size_t r8 = rowbase + (size_t)(wrow + g + 8) * Dn + 2 * t;
#pragma unroll
        for (int ks = 0; ks < 4; ks++) {
            int c = ks * 16;
            qfh[ks][0] = *(const uint32_t*)&gqh[r0 + c];
            qfh[ks][1] = *(const uint32_t*)&gqh[r8 + c];
            qfh[ks][2] = *(const uint32_t*)&gqh[r0 + c + 8];
            qfh[ks][3] = *(const uint32_t*)&gqh[r8 + c + 8];
            qfl[ks][0] = *(const uint32_t*)&gql[r0 + c];
            qfl[ks][1] = *(const uint32_t*)&gql[r8 + c];
            qfl[ks][2] = *(const uint32_t*)&gql[r0 + c + 8];
            qfl[ks][3] = *(const uint32_t*)&gql[r8 + c + 8];
        }
    }
    __syncthreads();

    const int qd0 = qdoc[wrow + g], qd8 = qdoc[wrow + g + 8];
    const int kv_begin = (srange[0] / 64) * 64;
    const int kv_end   = srange[1] + 1;

    const uint32_t ukh = s2u(sKh), ukl = s2u(sKl);
    const uint32_t uvh = s2u(sVh), uvl = s2u(sVl);
    const int brow = (lane & 7) + ((lane >> 4) << 3);
    const int bcol = ((lane >> 3) & 1) << 3;
    const uint32_t lmoff = (uint32_t)(((lane & 15) * AST + ((lane >> 4) << 3)) * 2);

    float o[8][4];
#pragma unroll
    for (int i = 0; i < 8; i++)
#pragma unroll
        for (int j = 0; j < 4; j++) o[i][j] = 0.f;
    float m0 = -1e30f, m8 = -1e30f, l0 = 0.f, l8 = 0.f;

    for (int k0 = kv_begin; k0 < kv_end; k0 += 64) {
        const size_t kb = (size_t)(b * Sn + k0) * Dn + h * HDn;
#pragma unroll
        for (int v = 0; v < 4; v++) {
            int e = tid + v * 128;
            int r = e >> 3, cg = (e & 7) * 8;
            size_t src = kb + (size_t)r * Dn + cg;
            uint32_t dst = (uint32_t)((r * AST + cg) * 2);
            cp16(ukh + dst, gkh + src);
            cp16(ukl + dst, gkl + src);
            cp16(uvh + dst, gvh + src);
            cp16(uvl + dst, gvl + src);
        }
        asm volatile("cp.async.commit_group;");
        if (tid < 64) kdoc[tid] = doc[k0 + tid];
        asm volatile("cp.async.wait_group 0;" ::: "memory");
        __syncthreads();

        float s[8][4];
#pragma unroll
        for (int i = 0; i < 8; i++)
#pragma unroll
            for (int j = 0; j < 4; j++) s[i][j] = 0.f;
#pragma unroll
        for (int ks = 0; ks < 4; ks++) {
#pragma unroll
            for (int np = 0; np < 2; np++) {
                uint32_t bh[2][4], bl[2][4];
#pragma unroll
                for (int q = 0; q < 2; q++) {
                    uint32_t koff = (uint32_t)((((np * 2 + q) * 16 + brow) * AST + ks * 16 + bcol) * 2);
                    LDSM_X4(bh[q][0], bh[q][1], bh[q][2], bh[q][3], ukh + koff);
                    LDSM_X4(bl[q][0], bl[q][1], bl[q][2], bl[q][3], ukl + koff);
                }
#pragma unroll
                for (int q = 0; q < 2; q++) {
                    mma16(s[4 * np + 2 * q],     qfh[ks], bh[q][0], bh[q][1]);
                    mma16(s[4 * np + 2 * q + 1], qfh[ks], bh[q][2], bh[q][3]);
                }
#pragma unroll
                for (int q = 0; q < 2; q++) {
                    mma16(s[4 * np + 2 * q],     qfh[ks], bl[q][0], bl[q][1]);
                    mma16(s[4 * np + 2 * q + 1], qfh[ks], bl[q][2], bl[q][3]);
                }
#pragma unroll
                for (int q = 0; q < 2; q++) {
                    mma16(s[4 * np + 2 * q],     qfl[ks], bh[q][0], bh[q][1]);
                    mma16(s[4 * np + 2 * q + 1], qfl[ks], bh[q][2], bh[q][3]);
                }
            }
        }

        float mx0 = -1e30f, mx8 = -1e30f;
#pragma unroll
        for (int nt = 0; nt < 8; nt++) {
            int kd0 = kdoc[nt * 8 + 2 * t], kd1 = kdoc[nt * 8 + 2 * t + 1];
            s[nt][0] = (qd0 == kd0) ? s[nt][0] * ATT_SCALE : -1e30f;
            s[nt][1] = (qd0 == kd1) ? s[nt][1] * ATT_SCALE : -1e30f;
            s[nt][2] = (qd8 == kd0) ? s[nt][2] * ATT_SCALE : -1e30f;
            s[nt][3] = (qd8 == kd1) ? s[nt][3] * ATT_SCALE : -1e30f;
            mx0 = fmaxf(mx0, fmaxf(s[nt][0], s[nt][1]));
            mx8 = fmaxf(mx8, fmaxf(s[nt][2], s[nt][3]));
        }
        mx0 = fmaxf(mx0, __shfl_xor_sync(0xffffffffu, mx0, 1));
        mx0 = fmaxf(mx0, __shfl_xor_sync(0xffffffffu, mx0, 2));
        mx8 = fmaxf(mx8, __shfl_xor_sync(0xffffffffu, mx8, 1));
        mx8 = fmaxf(mx8, __shfl_xor_sync(0xffffffffu, mx8, 2));
        const float mn0 = fmaxf(m0, mx0), mn8 = fmaxf(m8, mx8);
        const float f0 = __expf(m0 - mn0), f8 = __expf(m8 - mn8);
        float sum0 = 0.f, sum8 = 0.f;
#pragma unroll
        for (int nt = 0; nt < 8; nt++) {
            s[nt][0] = (s[nt][0] > -1e29f) ? __expf(s[nt][0] - mn0) : 0.f;
            s[nt][1] = (s[nt][1] > -1e29f) ? __expf(s[nt][1] - mn0) : 0.f;
            s[nt][2] = (s[nt][2] > -1e29f) ? __expf(s[nt][2] - mn8) : 0.f;
            s[nt][3] = (s[nt][3] > -1e29f) ? __expf(s[nt][3] - mn8) : 0.f;
            sum0 += s[nt][0] + s[nt][1];
            sum8 += s[nt][2] + s[nt][3];
        }
        sum0 += __shfl_xor_sync(0xffffffffu, sum0, 1);
        sum0 += __shfl_xor_sync(0xffffffffu, sum0, 2);
        sum8 += __shfl_xor_sync(0xffffffffu, sum8, 1);
        sum8 += __shfl_xor_sync(0xffffffffu, sum8, 2);
        l0 = l0 * f0 + sum0;  l8 = l8 * f8 + sum8;
        m0 = mn0;             m8 = mn8;
#pragma unroll
        for (int nt = 0; nt < 8; nt++) {
            o[nt][0] *= f0; o[nt][1] *= f0;
            o[nt][2] *= f8; o[nt][3] *= f8;
        }

#pragma unroll
        for (int ks = 0; ks < 4; ks++) {
            uint32_t pah[4], pal[4];
            pack_hl(pah[0], pal[0], s[2 * ks][0],     s[2 * ks][1]);
            pack_hl(pah[1], pal[1], s[2 * ks][2],     s[2 * ks][3]);
            pack_hl(pah[2], pal[2], s[2 * ks + 1][0], s[2 * ks + 1][1]);
            pack_hl(pah[3], pal[3], s[2 * ks + 1][2], s[2 * ks + 1][3]);
            uint32_t rowoff = (uint32_t)(ks * 16 * AST * 2) + lmoff;
#pragma unroll
            for (int dp = 0; dp < 2; dp++) {
                uint32_t vh[2][4], vl[2][4];
#pragma unroll
                for (int q = 0; q < 2; q++) {
                    uint32_t addr = rowoff + (uint32_t)((dp * 2 + q) * 16 * 2);
                    LDSM_X4_T(vh[q][0], vh[q][1], vh[q][2], vh[q][3], uvh + addr);
                    LDSM_X4_T(vl[q][0], vl[q][1], vl[q][2], vl[q][3], uvl + addr);
                }
#pragma unroll
                for (int q = 0; q < 2; q++) {
                    mma16(o[4 * dp + 2 * q],     pah, vh[q][0], vh[q][1]);
                    mma16(o[4 * dp + 2 * q + 1], pah, vh[q][2], vh[q][3]);
                }
#pragma unroll
                for (int q = 0; q < 2; q++) {
                    mma16(o[4 * dp + 2 * q],     pal, vh[q][0], vh[q][1]);
                    mma16(o[4 * dp + 2 * q + 1], pal, vh[q][2], vh[q][3]);
                }
#pragma unroll
                for (int q = 0; q < 2; q++) {
                    mma16(o[4 * dp + 2 * q],     pah, vl[q][0], vl[q][1]);
                    mma16(o[4 * dp + 2 * q + 1], pah, vl[q][2], vl[q][3]);
                }
            }
        }
        __syncthreads();
    }

    const float inv0 = 1.f / l0, inv8 = 1.f / l8;
    const size_t ob0 = rowbase + (size_t)(wrow + g) * Dn;
    const size_t ob8 = rowbase + (size_t)(wrow + g + 8) * Dn;
#pragma unroll
    for (int nt = 0; nt < 8; nt++) {
        int c = nt * 8 + 2 * t;
        uint32_t h0, l0r, h1, l1r;
        pack_hl(h0, l0r, o[nt][0] * inv0, o[nt][1] * inv0);
        pack_hl(h1, l1r, o[nt][2] * inv8, o[nt][3] * inv8);
        *(uint32_t*)&aoh[ob0 + c] = h0;
        *(uint32_t*)&aol[ob0 + c] = l0r;
        *(uint32_t*)&aoh[ob8 + c] = h1;
        *(uint32_t*)&aol[ob8 + c] = l1r;
    }
}

// ---------------------------------------------------------------------------
extern "C" void kernel_launch(void* const* d_in, const int* in_sizes, int n_in,
                              void* d_out, int out_size)
{
    (void)in_sizes; (void)n_in; (void)out_size;
    const float* x  = (const float*)d_in[0];
    const float* wq = (const float*)d_in[1];
    const float* bq = (const float*)d_in[2];
    const float* wk = (const float*)d_in[3];
    const float* bk = (const float*)d_in[4];
    const float* wv = (const float*)d_in[5];
    const float* bv = (const float*)d_in[6];
    const float* wo = (const float*)d_in[7];
    const float* bo = (const float*)d_in[8];
    const int*  doc = (const int*)d_in[9];
    float* out = (float*)d_out;

    int8_t *xa1, *xa2, *wq1, *wq2, *wk1, *wk2, *wv1, *wv2;
    unsigned* sc;
    __nv_bfloat16 *woh, *wol, *qh, *ql, *kh, *kl, *vh, *vl, *aoh, *aol;
    cudaGetSymbolAddress((void**)&xa1, g_xa1); cudaGetSymbolAddress((void**)&xa2, g_xa2);
    cudaGetSymbolAddress((void**)&wq1, g_wq1); cudaGetSymbolAddress((void**)&wq2, g_wq2);
    cudaGetSymbolAddress((void**)&wk1, g_wk1); cudaGetSymbolAddress((void**)&wk2, g_wk2);
    cudaGetSymbolAddress((void**)&wv1, g_wv1); cudaGetSymbolAddress((void**)&wv2, g_wv2);
    cudaGetSymbolAddress((void**)&sc,  g_scales);
    cudaGetSymbolAddress((void**)&woh, g_woh); cudaGetSymbolAddress((void**)&wol, g_wol);
    cudaGetSymbolAddress((void**)&qh, g_qh);   cudaGetSymbolAddress((void**)&ql, g_ql);
    cudaGetSymbolAddress((void**)&kh, g_kh);   cudaGetSymbolAddress((void**)&kl, g_kl);
    cudaGetSymbolAddress((void**)&vh, g_vh);   cudaGetSymbolAddress((void**)&vl, g_vl);
    cudaGetSymbolAddress((void**)&aoh, g_aoh); cudaGetSymbolAddress((void**)&aol, g_aol);

    const int nX = Mn * Dn, nW = Dn * Dn;
    zero_scales<<<1, 32>>>(sc);
    maxabs<<<512, 256>>>(x,  nX, sc + 0);
    maxabs<<<256, 256>>>(wq, nW, sc + 1);
    maxabs<<<256, 256>>>(wk, nW, sc + 2);
    maxabs<<<256, 256>>>(wv, nW, sc + 3);
    split_i8<<<(nX / 4 + 255) / 256, 256>>>((const float4*)x,  (char4*)xa1, (char4*)xa2, sc + 0, nX / 4);
    split_i8<<<(nW / 4 + 255) / 256, 256>>>((const float4*)wq, (char4*)wq1, (char4*)wq2, sc + 1, nW / 4);
    split_i8<<<(nW / 4 + 255) / 256, 256>>>((const float4*)wk, (char4*)wk1, (char4*)wk2, sc + 2, nW / 4);
    split_i8<<<(nW / 4 + 255) / 256, 256>>>((const float4*)wv, (char4*)wv1, (char4*)wv2, sc + 3, nW / 4);
    split_bf16<<<(nW / 4 + 255) / 256, 256>>>((const float4*)wo,
        (__nv_bfloat162*)woh, (__nv_bfloat162*)wol, nW / 4);

    const int i8_smem = 8 * IARR;   // 81920
    cudaFuncSetAttribute(gemm_i8_qkv, cudaFuncAttributeMaxDynamicSharedMemorySize, i8_smem);
    dim3 ggq(24, Mn / 128);
    gemm_i8_qkv<<<ggq, 256, i8_smem>>>(xa1, xa2,
        wq1, wq2, wk1, wk2, wv1, wv2, bq, bk, bv, sc,
        qh, ql, kh, kl, vh, vl, Mn, Dn, Dn);

    const int attn_smem = 4 * 64 * AST * (int)sizeof(__nv_bfloat16);
    cudaFuncSetAttribute(attn_mma, cudaFuncAttributeMaxDynamicSharedMemorySize, attn_smem);
    dim3 ga(Sn / 64, Hn, Bn);
    attn_mma<<<ga, 128, attn_smem>>>(qh, ql, kh, kl, vh, vl, doc, aoh, aol);

    const int o_smem = 8 * STAGE * (int)sizeof(__nv_bfloat16);   // 81920
    cudaFuncSetAttribute(gemm_bf16_o, cudaFuncAttributeMaxDynamicSharedMemorySize, o_smem);
    dim3 ggo(Dn / 128, Mn / 128);
    gemm_bf16_o<<<ggo, 256, o_smem>>>(aoh, aol, woh, wol, bo, out, Mn, Dn, Dn);
}

// round 11
// speedup vs baseline: 2.0691x; 2.0691x over previous
#include <cuda_runtime.h>
#include <cuda_bf16.h>
#include <cstdint>

#define Bn 2
#define Sn 2048
#define Dn 1024
#define Hn 16
#define HDn 64
#define Mn (Bn*Sn)
#define ATT_SCALE 0.125f   /* 64^-0.5 */

// bf16 hi/lo splits
static __device__ __nv_bfloat16 g_xh[(size_t)Mn*Dn],  g_xl[(size_t)Mn*Dn];
static __device__ __nv_bfloat16 g_wqh[(size_t)Dn*Dn], g_wql[(size_t)Dn*Dn];
static __device__ __nv_bfloat16 g_wkh[(size_t)Dn*Dn], g_wkl[(size_t)Dn*Dn];
static __device__ __nv_bfloat16 g_wvh[(size_t)Dn*Dn], g_wvl[(size_t)Dn*Dn];
static __device__ __nv_bfloat16 g_woh[(size_t)Dn*Dn], g_wol[(size_t)Dn*Dn];
static __device__ __nv_bfloat16 g_qh[(size_t)Mn*Dn],  g_ql[(size_t)Mn*Dn];
static __device__ __nv_bfloat16 g_kh[(size_t)Mn*Dn],  g_kl[(size_t)Mn*Dn];
static __device__ __nv_bfloat16 g_vh[(size_t)Mn*Dn],  g_vl[(size_t)Mn*Dn];
static __device__ __nv_bfloat16 g_aoh[(size_t)Mn*Dn], g_aol[(size_t)Mn*Dn];
static __device__ int g_docrange[32];   // [0..15]=start, [16..31]=end

// ---------------------------------------------------------------------------
// splits
// ---------------------------------------------------------------------------
__device__ __forceinline__ void split1(float4 v, __nv_bfloat162* hi,
                                       __nv_bfloat162* lo, int i) {
    __nv_bfloat16 hx = __float2bfloat16_rn(v.x);
    __nv_bfloat16 hy = __float2bfloat16_rn(v.y);
    __nv_bfloat16 hz = __float2bfloat16_rn(v.z);
    __nv_bfloat16 hw = __float2bfloat16_rn(v.w);
    hi[2 * i]     = __nv_bfloat162(hx, hy);
    hi[2 * i + 1] = __nv_bfloat162(hz, hw);
    lo[2 * i]     = __nv_bfloat162(__float2bfloat16_rn(v.x - __bfloat162float(hx)),
                                   __float2bfloat16_rn(v.y - __bfloat162float(hy)));
    lo[2 * i + 1] = __nv_bfloat162(__float2bfloat16_rn(v.z - __bfloat162float(hz)),
                                   __float2bfloat16_rn(v.w - __bfloat162float(hw)));
}

__global__ __launch_bounds__(256) void split_bf16(const float4* __restrict__ src,
    __nv_bfloat162* __restrict__ hi, __nv_bfloat162* __restrict__ lo, int n4)
{
    int i = blockIdx.x * 256 + threadIdx.x;
    if (i >= n4) return;
    split1(src[i], hi, lo, i);
}

__global__ __launch_bounds__(256) void split_w4(
    const float4* __restrict__ s0, const float4* __restrict__ s1,
    const float4* __restrict__ s2, const float4* __restrict__ s3,
    __nv_bfloat162* __restrict__ h0, __nv_bfloat162* __restrict__ l0,
    __nv_bfloat162* __restrict__ h1, __nv_bfloat162* __restrict__ l1,
    __nv_bfloat162* __restrict__ h2, __nv_bfloat162* __restrict__ l2,
    __nv_bfloat162* __restrict__ h3, __nv_bfloat162* __restrict__ l3, int n4)
{
    int i = blockIdx.x * 256 + threadIdx.x;
    if (i >= n4) return;
    int w = blockIdx.y;
    const float4* s = (w == 0) ? s0 : (w == 1) ? s1 : (w == 2) ? s2 : s3;
    __nv_bfloat162* h = (w == 0) ? h0 : (w == 1) ? h1 : (w == 2) ? h2 : h3;
    __nv_bfloat162* l = (w == 0) ? l0 : (w == 1) ? l1 : (w == 2) ? l2 : l3;
    split1(s[i], h, l, i);
}

// ---------------------------------------------------------------------------
// doc range precompute
// ---------------------------------------------------------------------------
__global__ void range_init(int* dr) {
    if (threadIdx.x < 16) { dr[threadIdx.x] = Sn; dr[16 + threadIdx.x] = 0; }
}
__global__ __launch_bounds__(256) void range_scan(const int* __restrict__ doc,
                                                  int* __restrict__ dr)
{
    int i = blockIdx.x * 256 + threadIdx.x;
    if (i >= Sn) return;
    int d = doc[i];
    atomicMin(&dr[d], i);
    atomicMax(&dr[16 + d], i);
}

// ---------------------------------------------------------------------------
// helpers
// ---------------------------------------------------------------------------
__device__ __forceinline__ uint32_t s2u(const void* p) {
    return (uint32_t)__cvta_generic_to_shared(p);
}

__device__ __forceinline__ void mma16(float* d, const uint32_t* a,
                                      uint32_t b0, uint32_t b1) {
    asm volatile(
        "mma.sync.aligned.m16n8k16.row.col.f32.bf16.bf16.f32 "
        "{%0,%1,%2,%3},{%4,%5,%6,%7},{%8,%9},{%0,%1,%2,%3};"
        : "+f"(d[0]), "+f"(d[1]), "+f"(d[2]), "+f"(d[3])
        : "r"(a[0]), "r"(a[1]), "r"(a[2]), "r"(a[3]), "r"(b0), "r"(b1));
}

__device__ __forceinline__ void cp16(uint32_t s, const void* g) {
    asm volatile("cp.async.cg.shared.global [%0], [%1], 16;" :: "r"(s), "l"(g));
}

__device__ __forceinline__ void pack_hl(uint32_t& hi, uint32_t& lo, float a, float b) {
    __nv_bfloat162 h = __float22bfloat162_rn(make_float2(a, b));
    float2 hf = __bfloat1622float2(h);
    __nv_bfloat162 l = __float22bfloat162_rn(make_float2(a - hf.x, b - hf.y));
    hi = *(uint32_t*)&h; lo = *(uint32_t*)&l;
}

#define LDSM_X4(r0,r1,r2,r3, addr) \
    asm volatile("ldmatrix.sync.aligned.m8n8.x4.shared.b16 {%0,%1,%2,%3}, [%4];" \
        : "=r"(r0), "=r"(r1), "=r"(r2), "=r"(r3) : "r"(addr))

#define LDSM_X4_T(r0,r1,r2,r3, addr) \
    asm volatile("ldmatrix.sync.aligned.m8n8.x4.trans.shared.b16 {%0,%1,%2,%3}, [%4];" \
        : "=r"(r0), "=r"(r1), "=r"(r2), "=r"(r3) : "r"(addr))

// ---------------------------------------------------------------------------
// 3xBF16 tensor-core GEMM (unified QKV / O). Block 128x128, KT=32, cp.async
// double-buffered, ldmatrix frags, term-major MMA order (RAW distance 8).
// ---------------------------------------------------------------------------
#define KT 32
#define PAD 40
#define STAGE (128 * PAD)

__global__ __launch_bounds__(256, 2) void gemm_uni(
    const __nv_bfloat16* __restrict__ Ah, const __nv_bfloat16* __restrict__ Al,
    const __nv_bfloat16* __restrict__ Bh0, const __nv_bfloat16* __restrict__ Bl0,
    const __nv_bfloat16* __restrict__ Bh1, const __nv_bfloat16* __restrict__ Bl1,
    const __nv_bfloat16* __restrict__ Bh2, const __nv_bfloat16* __restrict__ Bl2,
    const float* __restrict__ bias0, const float* __restrict__ bias1,
    const float* __restrict__ bias2,
    float* __restrict__ C,
    __nv_bfloat16* __restrict__ Ch0, __nv_bfloat16* __restrict__ Cl0,
    __nv_bfloat16* __restrict__ Ch1, __nv_bfloat16* __restrict__ Cl1,
    __nv_bfloat16* __restrict__ Ch2, __nv_bfloat16* __restrict__ Cl2,
    int M, int N, int K)
{
    extern __shared__ char dynsmem[];
    __nv_bfloat16* sm = (__nv_bfloat16*)dynsmem;
    __nv_bfloat16* sAh = sm;
    __nv_bfloat16* sAl = sm + 2 * STAGE;
    __nv_bfloat16* sBh = sm + 4 * STAGE;
    __nv_bfloat16* sBl = sm + 6 * STAGE;

    const int wsel = blockIdx.x >> 3;
    const __nv_bfloat16* Bh = (wsel == 0) ? Bh0 : (wsel == 1) ? Bh1 : Bh2;
    const __nv_bfloat16* Bl = (wsel == 0) ? Bl0 : (wsel == 1) ? Bl1 : Bl2;
    const float* bias = (wsel == 0) ? bias0 : (wsel == 1) ? bias1 : bias2;
    __nv_bfloat16* Ch = (wsel == 0) ? Ch0 : (wsel == 1) ? Ch1 : Ch2;
    __nv_bfloat16* Cl = (wsel == 0) ? Cl0 : (wsel == 1) ? Cl1 : Cl2;

    const int m0 = blockIdx.y * 128, n0 = (blockIdx.x & 7) * 128;
    const int tid = threadIdx.x;
    const int lane = tid & 31, wid = tid >> 5;
    const int g = lane >> 2, t = lane & 3;
    const int mBase = (wid & 3) * 32;
    const int nBase = (wid >> 2) * 64;

    const int lrow = tid >> 1;
    const int lcol = (tid & 1) * 16;

    const uint32_t sbase = s2u(sm);
    const uint32_t dAh = sbase + (uint32_t)(lrow * PAD + lcol) * 2;
    const uint32_t dAl = dAh + 2 * STAGE * 2;
    const uint32_t dBh = dAh + 4 * STAGE * 2;
    const uint32_t dBl = dAh + 6 * STAGE * 2;
    const __nv_bfloat16* gAh = Ah + (size_t)(m0 + lrow) * K + lcol;
    const __nv_bfloat16* gAl = Al + (size_t)(m0 + lrow) * K + lcol;
    const __nv_bfloat16* gBh = Bh + (size_t)(n0 + lrow) * K + lcol;
    const __nv_bfloat16* gBl = Bl + (size_t)(n0 + lrow) * K + lcol;

    const int arow = lane & 15;
    const int acol = (lane >> 4) << 3;
    const int brow = (lane & 7) + ((lane >> 4) << 3);
    const int bcol = ((lane >> 3) & 1) << 3;

    float acc[2][8][4];
#pragma unroll
    for (int i = 0; i < 2; i++)
#pragma unroll
        for (int j = 0; j < 8; j++)
#pragma unroll
            for (int l = 0; l < 4; l++) acc[i][j][l] = 0.f;

    const int nTiles = K / KT;

    auto issue = [&](int kt, int buf) {
        uint32_t so = (uint32_t)(buf * STAGE * 2);
#pragma unroll
        for (int c = 0; c < 2; c++) {
            cp16(dAh + so + c * 16, gAh + kt + c * 8);
            cp16(dAl + so + c * 16, gAl + kt + c * 8);
            cp16(dBh + so + c * 16, gBh + kt + c * 8);
            cp16(dBl + so + c * 16, gBl + kt + c * 8);
        }
        asm volatile("cp.async.commit_group;");
    };

    issue(0, 0);

    for (int tt = 0; tt < nTiles; tt++) {
        const int buf = tt & 1;
        if (tt + 1 < nTiles) {
            issue((tt + 1) * KT, buf ^ 1);
            asm volatile("cp.async.wait_group 1;");
        } else {
            asm volatile("cp.async.wait_group 0;");
        }
        __syncthreads();

        const uint32_t uAh = s2u(sAh + buf * STAGE);
        const uint32_t uAl = s2u(sAl + buf * STAGE);
        const uint32_t uBh = s2u(sBh + buf * STAGE);
        const uint32_t uBl = s2u(sBl + buf * STAGE);

#pragma unroll
        for (int k16 = 0; k16 < KT; k16 += 16) {
            uint32_t ah[2][4], al[2][4];
#pragma unroll
            for (int mt = 0; mt < 2; mt++) {
                uint32_t aoff = (uint32_t)(((mBase + mt * 16 + arow) * PAD + k16 + acol) * 2);
                LDSM_X4(ah[mt][0], ah[mt][1], ah[mt][2], ah[mt][3], uAh + aoff);
                LDSM_X4(al[mt][0], al[mt][1], al[mt][2], al[mt][3], uAl + aoff);
            }
#pragma unroll
            for (int np = 0; np < 2; np++) {
                uint32_t bh[2][4], bl[2][4];
#pragma unroll
                for (int q = 0; q < 2; q++) {
                    uint32_t boff = (uint32_t)(((nBase + (np * 2 + q) * 16 + brow) * PAD + k16 + bcol) * 2);
                    LDSM_X4(bh[q][0], bh[q][1], bh[q][2], bh[q][3], uBh + boff);
                    LDSM_X4(bl[q][0], bl[q][1], bl[q][2], bl[q][3], uBl + boff);
                }
#pragma unroll
                for (int q = 0; q < 2; q++)
#pragma unroll
                    for (int mt = 0; mt < 2; mt++) {
                        mma16(acc[mt][4 * np + 2 * q],     ah[mt], bh[q][0], bh[q][1]);
                        mma16(acc[mt][4 * np + 2 * q + 1], ah[mt], bh[q][2], bh[q][3]);
                    }
#pragma unroll
                for (int q = 0; q < 2; q++)
#pragma unroll
                    for (int mt = 0; mt < 2; mt++) {
                        mma16(acc[mt][4 * np + 2 * q],     ah[mt], bl[q][0], bl[q][1]);
                        mma16(acc[mt][4 * np + 2 * q + 1], ah[mt], bl[q][2], bl[q][3]);
                    }
#pragma unroll
                for (int q = 0; q < 2; q++)
#pragma unroll
                    for (int mt = 0; mt < 2; mt++) {
                        mma16(acc[mt][4 * np + 2 * q],     al[mt], bh[q][0], bh[q][1]);
                        mma16(acc[mt][4 * np + 2 * q + 1], al[mt], bh[q][2], bh[q][3]);
                    }
            }
        }
        __syncthreads();
    }

#pragma unroll
    for (int mt = 0; mt < 2; mt++) {
        int r0 = m0 + mBase + mt * 16 + g;
#pragma unroll
        for (int nt = 0; nt < 8; nt++) {
            int c = n0 + nBase + nt * 8 + 2 * t;
            float b0v = bias[c], b1v = bias[c + 1];
            float v00 = acc[mt][nt][0] + b0v, v01 = acc[mt][nt][1] + b1v;
            float v10 = acc[mt][nt][2] + b0v, v11 = acc[mt][nt][3] + b1v;
            if (C) {
                *(float2*)&C[(size_t)r0 * N + c] = make_float2(v00, v01);
                *(float2*)&C[(size_t)(r0 + 8) * N + c] = make_float2(v10, v11);
            } else {
                uint32_t h0, l0, h1, l1;
                pack_hl(h0, l0, v00, v01);
                pack_hl(h1, l1, v10, v11);
                *(uint32_t*)&Ch[(size_t)r0 * N + c] = h0;
                *(uint32_t*)&Cl[(size_t)r0 * N + c] = l0;
                *(uint32_t*)&Ch[(size_t)(r0 + 8) * N + c] = h1;
                *(uint32_t*)&Cl[(size_t)(r0 + 8) * N + c] = l1;
            }
        }
    }
}

// ---------------------------------------------------------------------------
// Tensor-core flash attention, doc-block mask + precomputed KV ranges.
// Double-buffered cp.async KV pipeline (2 stages), term-major MMA order.
// ---------------------------------------------------------------------------
#define AST 72
#define ASB (4 * 64 * AST * 2)   /* bytes per stage: Kh,Kl,Vh,Vl */

__global__ __launch_bounds__(128, 3) void attn_mma(
    const __nv_bfloat16* __restrict__ gqh, const __nv_bfloat16* __restrict__ gql,
    const __nv_bfloat16* __restrict__ gkh, const __nv_bfloat16* __restrict__ gkl,
    const __nv_bfloat16* __restrict__ gvh, const __nv_bfloat16* __restrict__ gvl,
    const int* __restrict__ doc, const int* __restrict__ dr,
    __nv_bfloat16* __restrict__ aoh, __nv_bfloat16* __restrict__ aol)
{
    extern __shared__ char dynsmem[];
    __shared__ int qdoc[64], kdoc[2][64];

    const int q0 = blockIdx.x * 64;
    const int h = blockIdx.y, b = blockIdx.z;
    const int tid = threadIdx.x;
    const int lane = tid & 31, w = tid >> 5;
    const int g = lane >> 2, t = lane & 3;
    const int wrow = w * 16;

    if (tid < 64) qdoc[tid] = doc[q0 + tid];

    // Q fragments directly from global (once per block)
    const size_t rowbase = (size_t)(b * Sn + q0) * Dn + h * HDn;
    uint32_t qfh[4][4], qfl[4][4];
    {
        const size_t r0 = rowbase + (size_t)(wrow + g) * Dn + 2 * t;
        const size_t r8 = rowbase + (size_t)(wrow + g + 8) * Dn + 2 * t;
#pragma unroll
        for (int ks = 0; ks < 4; ks++) {
            int c = ks * 16;
            qfh[ks][0] = *(const uint32_t*)&gqh[r0 + c];
            qfh[ks][1] = *(const uint32_t*)&gqh[r8 + c];
            qfh[ks][2] = *(const uint32_t*)&gqh[r0 + c + 8];
            qfh[ks][3] = *(const uint32_t*)&gqh[r8 + c + 8];
            qfl[ks][0] = *(const uint32_t*)&gql[r0 + c];
            qfl[ks][1] = *(const uint32_t*)&gql[r8 + c];
            qfl[ks][2] = *(const uint32_t*)&gql[r0 + c + 8];
            qfl[ks][3] = *(const uint32_t*)&gql[r8 + c + 8];
        }
    }
    __syncthreads();   // qdoc ready

    const int qd0 = qdoc[wrow + g], qd8 = qdoc[wrow + g + 8];
    const int kv_begin = (__ldg(&dr[qdoc[0]]) / 64) * 64;
    const int kv_end   = __ldg(&dr[16 + qdoc[63]]) + 1;
    const int nT = (kv_end - kv_begin + 63) / 64;

    const uint32_t sb0 = s2u(dynsmem);
    const int brow = (lane & 7) + ((lane >> 4) << 3);
    const int bcol = ((lane >> 3) & 1) << 3;
    const uint32_t lmoff = (uint32_t)(((lane & 15) * AST + ((lane >> 4) << 3)) * 2);

    // stage loader: tile tt -> buffer tt&1
    auto stage = [&](int tt) {
        const int buf = tt & 1;
        const int k0 = kv_begin + tt * 64;
        if (tid < 64) kdoc[buf][tid] = doc[k0 + tid];
        const size_t kb = (size_t)(b * Sn + k0) * Dn + h * HDn;
        const uint32_t sst = sb0 + (uint32_t)buf * ASB;
#pragma unroll
        for (int v = 0; v < 4; v++) {
            int e = tid + v * 128;
            int r = e >> 3, cg = (e & 7) * 8;
            size_t src = kb + (size_t)r * Dn + cg;
            uint32_t dst = sst + (uint32_t)((r * AST + cg) * 2);
            cp16(dst,                       gkh + src);
            cp16(dst + 1 * 64 * AST * 2,    gkl + src);
            cp16(dst + 2 * 64 * AST * 2,    gvh + src);
            cp16(dst + 3 * 64 * AST * 2,    gvl + src);
        }
        asm volatile("cp.async.commit_group;");
    };

    float o[8][4];
#pragma unroll
    for (int i = 0; i < 8; i++)
#pragma unroll
        for (int j = 0; j < 4; j++) o[i][j] = 0.f;
    float m0 = -1e30f, m8 = -1e30f, l0 = 0.f, l8 = 0.f;

    stage(0);

    for (int tt = 0; tt < nT; tt++) {
        const int buf = tt & 1;
        if (tt + 1 < nT) {
            stage(tt + 1);
            asm volatile("cp.async.wait_group 1;" ::: "memory");
        } else {
            asm volatile("cp.async.wait_group 0;" ::: "memory");
        }
        __syncthreads();

        const uint32_t ukh = sb0 + (uint32_t)buf * ASB;
        const uint32_t ukl = ukh + 1 * 64 * AST * 2;
        const uint32_t uvh = ukh + 2 * 64 * AST * 2;
        const uint32_t uvl = ukh + 3 * 64 * AST * 2;

        // S = Q K^T (3-split), term-major per n-pair (RAW distance 4)
        float s[8][4];
#pragma unroll
        for (int i = 0; i < 8; i++)
#pragma unroll
            for (int j = 0; j < 4; j++) s[i][j] = 0.f;
#pragma unroll
        for (int ks = 0; ks < 4; ks++) {
#pragma unroll
            for (int np = 0; np < 2; np++) {
                uint32_t bh[2][4], bl[2][4];
#pragma unroll
                for (int q = 0; q < 2; q++) {
                    uint32_t koff = (uint32_t)((((np * 2 + q) * 16 + brow) * AST + ks * 16 + bcol) * 2);
                    LDSM_X4(bh[q][0], bh[q][1], bh[q][2], bh[q][3], ukh + koff);
                    LDSM_X4(bl[q][0], bl[q][1], bl[q][2], bl[q][3], ukl + koff);
                }
#pragma unroll
                for (int q = 0; q < 2; q++) {
                    mma16(s[4 * np + 2 * q],     qfh[ks], bh[q][0], bh[q][1]);
                    mma16(s[4 * np + 2 * q + 1], qfh[ks], bh[q][2], bh[q][3]);
                }
#pragma unroll
                for (int q = 0; q < 2; q++) {
                    mma16(s[4 * np + 2 * q],     qfh[ks], bl[q][0], bl[q][1]);
                    mma16(s[4 * np + 2 * q + 1], qfh[ks], bl[q][2], bl[q][3]);
                }
#pragma unroll
                for (int q = 0; q < 2; q++) {
                    mma16(s[4 * np + 2 * q],     qfl[ks], bh[q][0], bh[q][1]);
                    mma16(s[4 * np + 2 * q + 1], qfl[ks], bh[q][2], bh[q][3]);
                }
            }
        }

        float mx0 = -1e30f, mx8 = -1e30f;
#pragma unroll
        for (int nt = 0; nt < 8; nt++) {
            int kd0 = kdoc[buf][nt * 8 + 2 * t], kd1 = kdoc[buf][nt * 8 + 2 * t + 1];
            s[nt][0] = (qd0 == kd0) ? s[nt][0] * ATT_SCALE : -1e30f;
            s[nt][1] = (qd0 == kd1) ? s[nt][1] * ATT_SCALE : -1e30f;
            s[nt][2] = (qd8 == kd0) ? s[nt][2] * ATT_SCALE : -1e30f;
            s[nt][3] = (qd8 == kd1) ? s[nt][3] * ATT_SCALE : -1e30f;
            mx0 = fmaxf(mx0, fmaxf(s[nt][0], s[nt][1]));
            mx8 = fmaxf(mx8, fmaxf(s[nt][2], s[nt][3]));
        }
        mx0 = fmaxf(mx0, __shfl_xor_sync(0xffffffffu, mx0, 1));
        mx0 = fmaxf(mx0, __shfl_xor_sync(0xffffffffu, mx0, 2));
        mx8 = fmaxf(mx8, __shfl_xor_sync(0xffffffffu, mx8, 1));
        mx8 = fmaxf(mx8, __shfl_xor_sync(0xffffffffu, mx8, 2));
        const float mn0 = fmaxf(m0, mx0), mn8 = fmaxf(m8, mx8);
        const float f0 = __expf(m0 - mn0), f8 = __expf(m8 - mn8);
        float sum0 = 0.f, sum8 = 0.f;
#pragma unroll
        for (int nt = 0; nt < 8; nt++) {
            s[nt][0] = (s[nt][0] > -1e29f) ? __expf(s[nt][0] - mn0) : 0.f;
            s[nt][1] = (s[nt][1] > -1e29f) ? __expf(s[nt][1] - mn0) : 0.f;
            s[nt][2] = (s[nt][2] > -1e29f) ? __expf(s[nt][2] - mn8) : 0.f;
            s[nt][3] = (s[nt][3] > -1e29f) ? __expf(s[nt][3] - mn8) : 0.f;
            sum0 += s[nt][0] + s[nt][1];
            sum8 += s[nt][2] + s[nt][3];
        }
        sum0 += __shfl_xor_sync(0xffffffffu, sum0, 1);
        sum0 += __shfl_xor_sync(0xffffffffu, sum0, 2);
        sum8 += __shfl_xor_sync(0xffffffffu, sum8, 1);
        sum8 += __shfl_xor_sync(0xffffffffu, sum8, 2);
        l0 = l0 * f0 + sum0;  l8 = l8 * f8 + sum8;
        m0 = mn0;             m8 = mn8;
#pragma unroll
        for (int nt = 0; nt < 8; nt++) {
            o[nt][0] *= f0; o[nt][1] *= f0;
            o[nt][2] *= f8; o[nt][3] *= f8;
        }

        // O += P V (3-split), term-major per d-pair (RAW distance 4)
#pragma unroll
        for (int ks = 0; ks < 4; ks++) {
            uint32_t pah[4], pal[4];
            pack_hl(pah[0], pal[0], s[2 * ks][0],     s[2 * ks][1]);
            pack_hl(pah[1], pal[1], s[2 * ks][2],     s[2 * ks][3]);
            pack_hl(pah[2], pal[2], s[2 * ks + 1][0], s[2 * ks + 1][1]);
            pack_hl(pah[3], pal[3], s[2 * ks + 1][2], s[2 * ks + 1][3]);
            uint32_t rowoff = (uint32_t)(ks * 16 * AST * 2) + lmoff;
#pragma unroll
            for (int dp = 0; dp < 2; dp++) {
                uint32_t vh[2][4], vl[2][4];
#pragma unroll
                for (int q = 0; q < 2; q++) {
                    uint32_t addr = rowoff + (uint32_t)((dp * 2 + q) * 16 * 2);
                    LDSM_X4_T(vh[q][0], vh[q][1], vh[q][2], vh[q][3], uvh + addr);
                    LDSM_X4_T(vl[q][0], vl[q][1], vl[q][2], vl[q][3], uvl + addr);
                }
#pragma unroll
                for (int q = 0; q < 2; q++) {
                    mma16(o[4 * dp + 2 * q],     pah, vh[q][0], vh[q][1]);
                    mma16(o[4 * dp + 2 * q + 1], pah, vh[q][2], vh[q][3]);
                }
#pragma unroll
                for (int q = 0; q < 2; q++) {
                    mma16(o[4 * dp + 2 * q],     pal, vh[q][0], vh[q][1]);
                    mma16(o[4 * dp + 2 * q + 1], pal, vh[q][2], vh[q][3]);
                }
#pragma unroll
                for (int q = 0; q < 2; q++) {
                    mma16(o[4 * dp + 2 * q],     pah, vl[q][0], vl[q][1]);
                    mma16(o[4 * dp + 2 * q + 1], pah, vl[q][2], vl[q][3]);
                }
            }
        }
        __syncthreads();   // all reads of buf done before it is restaged
    }

    const float inv0 = 1.f / l0, inv8 = 1.f / l8;
    const size_t ob0 = rowbase + (size_t)(wrow + g) * Dn;
    const size_t ob8 = rowbase + (size_t)(wrow + g + 8) * Dn;
#pragma unroll
    for (int nt = 0; nt < 8; nt++) {
        int c = nt * 8 + 2 * t;
        uint32_t h0, l0r, h1, l1r;
        pack_hl(h0, l0r, o[nt][0] * inv0, o[nt][1] * inv0);
        pack_hl(h1, l1r, o[nt][2] * inv8, o[nt][3] * inv8);
        *(uint32_t*)&aoh[ob0 + c] = h0;
        *(uint32_t*)&aol[ob0 + c] = l0r;
        *(uint32_t*)&aoh[ob8 + c] = h1;
        *(uint32_t*)&aol[ob8 + c] = l1r;
    }
}

// ---------------------------------------------------------------------------
extern "C" void kernel_launch(void* const* d_in, const int* in_sizes, int n_in,
                              void* d_out, int out_size)
{
    (void)in_sizes; (void)n_in; (void)out_size;
    const float* x  = (const float*)d_in[0];
    const float* wq = (const float*)d_in[1];
    const float* bq = (const float*)d_in[2];
    const float* wk = (const float*)d_in[3];
    const float* bk = (const float*)d_in[4];
    const float* wv = (const float*)d_in[5];
    const float* bv = (const float*)d_in[6];
    const float* wo = (const float*)d_in[7];
    const float* bo = (const float*)d_in[8];
    const int*  doc = (const int*)d_in[9];
    float* out = (float*)d_out;

    __nv_bfloat16 *xh, *xl, *wqh, *wql, *wkh, *wkl, *wvh, *wvl, *woh, *wol;
    __nv_bfloat16 *qh, *ql, *kh, *kl, *vh, *vl, *aoh, *aol;
    int* dr;
    cudaGetSymbolAddress((void**)&xh, g_xh);   cudaGetSymbolAddress((void**)&xl, g_xl);
    cudaGetSymbolAddress((void**)&wqh, g_wqh); cudaGetSymbolAddress((void**)&wql, g_wql);
    cudaGetSymbolAddress((void**)&wkh, g_wkh); cudaGetSymbolAddress((void**)&wkl, g_wkl);
    cudaGetSymbolAddress((void**)&wvh, g_wvh); cudaGetSymbolAddress((void**)&wvl, g_wvl);
    cudaGetSymbolAddress((void**)&woh, g_woh); cudaGetSymbolAddress((void**)&wol, g_wol);
    cudaGetSymbolAddress((void**)&qh, g_qh);   cudaGetSymbolAddress((void**)&ql, g_ql);
    cudaGetSymbolAddress((void**)&kh, g_kh);   cudaGetSymbolAddress((void**)&kl, g_kl);
    cudaGetSymbolAddress((void**)&vh, g_vh);   cudaGetSymbolAddress((void**)&vl, g_vl);
    cudaGetSymbolAddress((void**)&aoh, g_aoh); cudaGetSymbolAddress((void**)&aol, g_aol);
    cudaGetSymbolAddress((void**)&dr,  g_docrange);

    const int nX4 = Mn * Dn / 4, nW4 = Dn * Dn / 4;
    split_bf16<<<(nX4 + 255) / 256, 256>>>((const float4*)x,
        (__nv_bfloat162*)xh, (__nv_bfloat162*)xl, nX4);
    dim3 gw((nW4 + 255) / 256, 4);
    split_w4<<<gw, 256>>>((const float4*)wq, (const float4*)wk,
        (const float4*)wv, (const float4*)wo,
        (__nv_bfloat162*)wqh, (__nv_bfloat162*)wql,
        (__nv_bfloat162*)wkh, (__nv_bfloat162*)wkl,
        (__nv_bfloat162*)wvh, (__nv_bfloat162*)wvl,
        (__nv_bfloat162*)woh, (__nv_bfloat162*)wol, nW4);
    range_init<<<1, 32>>>(dr);
    range_scan<<<Sn / 256, 256>>>(doc, dr);

    const int gemm_smem = 8 * STAGE * (int)sizeof(__nv_bfloat16);  // 81920
    cudaFuncSetAttribute(gemm_uni, cudaFuncAttributeMaxDynamicSharedMemorySize, gemm_smem);

    // fused QKV
    dim3 ggq(24, Mn / 128);
    gemm_uni<<<ggq, 256, gemm_smem>>>(xh, xl,
        wqh, wql, wkh, wkl, wvh, wvl, bq, bk, bv,
        nullptr, qh, ql, kh, kl, vh, vl, Mn, Dn, Dn);

    const int attn_smem = 2 * ASB;   // 73728
    cudaFuncSetAttribute(attn_mma, cudaFuncAttributeMaxDynamicSharedMemorySize, attn_smem);
    dim3 ga(Sn / 64, Hn, Bn);
    attn_mma<<<ga, 128, attn_smem>>>(qh, ql, kh, kl, vh, vl, doc, dr, aoh, aol);

    // O projection (fp32 out)
    dim3 ggo(8, Mn / 128);
    gemm_uni<<<ggo, 256, gemm_smem>>>(aoh, aol,
        woh, wol, woh, wol, woh, wol, bo, bo, bo,
        out, nullptr, nullptr, nullptr, nullptr, nullptr, nullptr, Mn, Dn, Dn);
}

// round 12
// speedup vs baseline: 4.2341x; 2.0464x over previous
#include <cuda_runtime.h>
#include <cuda_fp16.h>
#include <cstdint>

#define Bn 2
#define Sn 2048
#define Dn 1024
#define Hn 16
#define HDn 64
#define Mn (Bn*Sn)
#define ATT_SCALE 0.125f   /* 64^-0.5 */

// fp16 tensors
static __device__ __half g_xh[(size_t)Mn*Dn];
static __device__ __half g_wqh[(size_t)Dn*Dn], g_wkh[(size_t)Dn*Dn];
static __device__ __half g_wvh[(size_t)Dn*Dn], g_woh[(size_t)Dn*Dn];
static __device__ __half g_qh[(size_t)Mn*Dn], g_kh[(size_t)Mn*Dn], g_vh[(size_t)Mn*Dn];
static __device__ __half g_aoh[(size_t)Mn*Dn];
static __device__ int g_docrange[32];   // [0..15]=start, [16..31]=end

// ---------------------------------------------------------------------------
// fp32 -> fp16 converts
// ---------------------------------------------------------------------------
__global__ __launch_bounds__(256) void cvt_f16(const float4* __restrict__ src,
    __half2* __restrict__ dst, int n4)
{
    int i = blockIdx.x * 256 + threadIdx.x;
    if (i >= n4) return;
    float4 v = src[i];
    dst[2 * i]     = __float22half2_rn(make_float2(v.x, v.y));
    dst[2 * i + 1] = __float22half2_rn(make_float2(v.z, v.w));
}

__global__ __launch_bounds__(256) void cvt_w4(
    const float4* __restrict__ s0, const float4* __restrict__ s1,
    const float4* __restrict__ s2, const float4* __restrict__ s3,
    __half2* __restrict__ d0, __half2* __restrict__ d1,
    __half2* __restrict__ d2, __half2* __restrict__ d3, int n4)
{
    int i = blockIdx.x * 256 + threadIdx.x;
    if (i >= n4) return;
    int w = blockIdx.y;
    const float4* s = (w == 0) ? s0 : (w == 1) ? s1 : (w == 2) ? s2 : s3;
    __half2* d = (w == 0) ? d0 : (w == 1) ? d1 : (w == 2) ? d2 : d3;
    float4 v = s[i];
    d[2 * i]     = __float22half2_rn(make_float2(v.x, v.y));
    d[2 * i + 1] = __float22half2_rn(make_float2(v.z, v.w));
}

// ---------------------------------------------------------------------------
// doc range precompute
// ---------------------------------------------------------------------------
__global__ void range_init(int* dr) {
    if (threadIdx.x < 16) { dr[threadIdx.x] = Sn; dr[16 + threadIdx.x] = 0; }
}
__global__ __launch_bounds__(256) void range_scan(const int* __restrict__ doc,
                                                  int* __restrict__ dr)
{
    int i = blockIdx.x * 256 + threadIdx.x;
    if (i >= Sn) return;
    int d = doc[i];
    atomicMin(&dr[d], i);
    atomicMax(&dr[16 + d], i);
}

// ---------------------------------------------------------------------------
// helpers
// ---------------------------------------------------------------------------
__device__ __forceinline__ uint32_t s2u(const void* p) {
    return (uint32_t)__cvta_generic_to_shared(p);
}

__device__ __forceinline__ void mmah(float* d, const uint32_t* a,
                                     uint32_t b0, uint32_t b1) {
    asm volatile(
        "mma.sync.aligned.m16n8k16.row.col.f32.f16.f16.f32 "
        "{%0,%1,%2,%3},{%4,%5,%6,%7},{%8,%9},{%0,%1,%2,%3};"
        : "+f"(d[0]), "+f"(d[1]), "+f"(d[2]), "+f"(d[3])
        : "r"(a[0]), "r"(a[1]), "r"(a[2]), "r"(a[3]), "r"(b0), "r"(b1));
}

__device__ __forceinline__ void cp16(uint32_t s, const void* g) {
    asm volatile("cp.async.cg.shared.global [%0], [%1], 16;" :: "r"(s), "l"(g));
}

__device__ __forceinline__ uint32_t packh(float a, float b) {
    __half2 h = __float22half2_rn(make_float2(a, b));
    return *(uint32_t*)&h;
}

#define LDSM_X4(r0,r1,r2,r3, addr) \
    asm volatile("ldmatrix.sync.aligned.m8n8.x4.shared.b16 {%0,%1,%2,%3}, [%4];" \
        : "=r"(r0), "=r"(r1), "=r"(r2), "=r"(r3) : "r"(addr))

#define LDSM_X4_T(r0,r1,r2,r3, addr) \
    asm volatile("ldmatrix.sync.aligned.m8n8.x4.trans.shared.b16 {%0,%1,%2,%3}, [%4];" \
        : "=r"(r0), "=r"(r1), "=r"(r2), "=r"(r3) : "r"(addr))

// ---------------------------------------------------------------------------
// Single-fp16 tensor-core GEMM (unified QKV / O). Block 128x128, KT=32,
// cp.async double-buffered, ldmatrix frags. C = A @ W^T + bias.
// ---------------------------------------------------------------------------
#define KT 32
#define PAD 40
#define STAGE (128 * PAD)   /* halves per array per stage */

__global__ __launch_bounds__(256, 2) void gemm_f16(
    const __half* __restrict__ A,
    const __half* __restrict__ B0, const __half* __restrict__ B1,
    const __half* __restrict__ B2,
    const float* __restrict__ bias0, const float* __restrict__ bias1,
    const float* __restrict__ bias2,
    float* __restrict__ C,
    __half* __restrict__ C0, __half* __restrict__ C1, __half* __restrict__ C2,
    int M, int N, int K)
{
    extern __shared__ char dynsmem[];
    __half* sm = (__half*)dynsmem;
    __half* sA = sm;                 // [2][128][PAD]
    __half* sB = sm + 2 * STAGE;

    const int wsel = blockIdx.x >> 3;
    const __half* B = (wsel == 0) ? B0 : (wsel == 1) ? B1 : B2;
    const float* bias = (wsel == 0) ? bias0 : (wsel == 1) ? bias1 : bias2;
    __half* Co = (wsel == 0) ? C0 : (wsel == 1) ? C1 : C2;

    const int m0 = blockIdx.y * 128, n0 = (blockIdx.x & 7) * 128;
    const int tid = threadIdx.x;
    const int lane = tid & 31, wid = tid >> 5;
    const int g = lane >> 2, t = lane & 3;
    const int mBase = (wid & 3) * 32;
    const int nBase = (wid >> 2) * 64;

    const int lrow = tid >> 1;
    const int lcol = (tid & 1) * 16;

    const uint32_t sbase = s2u(sm);
    const uint32_t dA = sbase + (uint32_t)(lrow * PAD + lcol) * 2;
    const uint32_t dB = dA + 2 * STAGE * 2;
    const __half* gA = A + (size_t)(m0 + lrow) * K + lcol;
    const __half* gB = B + (size_t)(n0 + lrow) * K + lcol;

    const int arow = lane & 15;
    const int acol = (lane >> 4) << 3;
    const int brow = (lane & 7) + ((lane >> 4) << 3);
    const int bcol = ((lane >> 3) & 1) << 3;

    float acc[2][8][4];
#pragma unroll
    for (int i = 0; i < 2; i++)
#pragma unroll
        for (int j = 0; j < 8; j++)
#pragma unroll
            for (int l = 0; l < 4; l++) acc[i][j][l] = 0.f;

    const int nTiles = K / KT;

    auto issue = [&](int kt, int buf) {
        uint32_t so = (uint32_t)(buf * STAGE * 2);
#pragma unroll
        for (int c = 0; c < 2; c++) {
            cp16(dA + so + c * 16, gA + kt + c * 8);
            cp16(dB + so + c * 16, gB + kt + c * 8);
        }
        asm volatile("cp.async.commit_group;");
    };

    issue(0, 0);

    for (int tt = 0; tt < nTiles; tt++) {
        const int buf = tt & 1;
        if (tt + 1 < nTiles) {
            issue((tt + 1) * KT, buf ^ 1);
            asm volatile("cp.async.wait_group 1;");
        } else {
            asm volatile("cp.async.wait_group 0;");
        }
        __syncthreads();

        const uint32_t uA = s2u(sA + buf * STAGE);
        const uint32_t uB = s2u(sB + buf * STAGE);

#pragma unroll
        for (int k16 = 0; k16 < KT; k16 += 16) {
            uint32_t af[2][4];
#pragma unroll
            for (int mt = 0; mt < 2; mt++) {
                uint32_t aoff = (uint32_t)(((mBase + mt * 16 + arow) * PAD + k16 + acol) * 2);
                LDSM_X4(af[mt][0], af[mt][1], af[mt][2], af[mt][3], uA + aoff);
            }
#pragma unroll
            for (int np = 0; np < 2; np++) {
                uint32_t bf[2][4];
#pragma unroll
                for (int q = 0; q < 2; q++) {
                    uint32_t boff = (uint32_t)(((nBase + (np * 2 + q) * 16 + brow) * PAD + k16 + bcol) * 2);
                    LDSM_X4(bf[q][0], bf[q][1], bf[q][2], bf[q][3], uB + boff);
                }
#pragma unroll
                for (int q = 0; q < 2; q++)
#pragma unroll
                    for (int mt = 0; mt < 2; mt++) {
                        mmah(acc[mt][4 * np + 2 * q],     af[mt], bf[q][0], bf[q][1]);
                        mmah(acc[mt][4 * np + 2 * q + 1], af[mt], bf[q][2], bf[q][3]);
                    }
            }
        }
        __syncthreads();
    }

#pragma unroll
    for (int mt = 0; mt < 2; mt++) {
        int r0 = m0 + mBase + mt * 16 + g;
#pragma unroll
        for (int nt = 0; nt < 8; nt++) {
            int c = n0 + nBase + nt * 8 + 2 * t;
            float b0v = bias[c], b1v = bias[c + 1];
            float v00 = acc[mt][nt][0] + b0v, v01 = acc[mt][nt][1] + b1v;
            float v10 = acc[mt][nt][2] + b0v, v11 = acc[mt][nt][3] + b1v;
            if (C) {
                *(float2*)&C[(size_t)r0 * N + c] = make_float2(v00, v01);
                *(float2*)&C[(size_t)(r0 + 8) * N + c] = make_float2(v10, v11);
            } else {
                *(uint32_t*)&Co[(size_t)r0 * N + c] = packh(v00, v01);
                *(uint32_t*)&Co[(size_t)(r0 + 8) * N + c] = packh(v10, v11);
            }
        }
    }
}

// ---------------------------------------------------------------------------
// Single-fp16 tensor-core flash attention, doc-block mask + precomputed
// KV ranges. Double-buffered cp.async KV pipeline.
// ---------------------------------------------------------------------------
#define AST 72
#define ASB (2 * 64 * AST * 2)   /* bytes per stage: K, V */

__global__ __launch_bounds__(128, 3) void attn_f16(
    const __half* __restrict__ gq, const __half* __restrict__ gk,
    const __half* __restrict__ gv,
    const int* __restrict__ doc, const int* __restrict__ dr,
    __half* __restrict__ ao)
{
    extern __shared__ char dynsmem[];
    __shared__ int qdoc[64], kdoc[2][64];

    const int q0 = blockIdx.x * 64;
    const int h = blockIdx.y, b = blockIdx.z;
    const int tid = threadIdx.x;
    const int lane = tid & 31, w = tid >> 5;
    const int g = lane >> 2, t = lane & 3;
    const int wrow = w * 16;

    if (tid < 64) qdoc[tid] = doc[q0 + tid];

    // Q fragments directly from global
    const size_t rowbase = (size_t)(b * Sn + q0) * Dn + h * HDn;
    uint32_t qf[4][4];
    {
        const size_t r0 = rowbase + (size_t)(wrow + g) * Dn + 2 * t;
        const size_t r8 = rowbase + (size_t)(wrow + g + 8) * Dn + 2 * t;
#pragma unroll
        for (int ks = 0; ks < 4; ks++) {
            int c = ks * 16;
            qf[ks][0] = *(const uint32_t*)&gq[r0 + c];
            qf[ks][1] = *(const uint32_t*)&gq[r8 + c];
            qf[ks][2] = *(const uint32_t*)&gq[r0 + c + 8];
            qf[ks][3] = *(const uint32_t*)&gq[r8 + c + 8];
        }
    }
    __syncthreads();   // qdoc ready

    const int qd0 = qdoc[wrow + g], qd8 = qdoc[wrow + g + 8];
    const int kv_begin = (__ldg(&dr[qdoc[0]]) / 64) * 64;
    const int kv_end   = __ldg(&dr[16 + qdoc[63]]) + 1;
    const int nT = (kv_end - kv_begin + 63) / 64;

    const uint32_t sb0 = s2u(dynsmem);
    const int brow = (lane & 7) + ((lane >> 4) << 3);
    const int bcol = ((lane >> 3) & 1) << 3;
    const uint32_t lmoff = (uint32_t)(((lane & 15) * AST + ((lane >> 4) << 3)) * 2);

    auto stage = [&](int tt) {
        const int buf = tt & 1;
        const int k0 = kv_begin + tt * 64;
        if (tid < 64) kdoc[buf][tid] = doc[k0 + tid];
        const size_t kb = (size_t)(b * Sn + k0) * Dn + h * HDn;
        const uint32_t sst = sb0 + (uint32_t)buf * ASB;
#pragma unroll
        for (int v = 0; v < 4; v++) {
            int e = tid + v * 128;
            int r = e >> 3, cg = (e & 7) * 8;
            size_t src = kb + (size_t)r * Dn + cg;
            uint32_t dst = sst + (uint32_t)((r * AST + cg) * 2);
            cp16(dst,                    gk + src);
            cp16(dst + 64 * AST * 2,     gv + src);
        }
        asm volatile("cp.async.commit_group;");
    };

    float o[8][4];
#pragma unroll
    for (int i = 0; i < 8; i++)
#pragma unroll
        for (int j = 0; j < 4; j++) o[i][j] = 0.f;
    float m0 = -1e30f, m8 = -1e30f, l0 = 0.f, l8 = 0.f;

    stage(0);

    for (int tt = 0; tt < nT; tt++) {
        const int buf = tt & 1;
        if (tt + 1 < nT) {
            stage(tt + 1);
            asm volatile("cp.async.wait_group 1;" ::: "memory");
        } else {
            asm volatile("cp.async.wait_group 0;" ::: "memory");
        }
        __syncthreads();

        const uint32_t uk = sb0 + (uint32_t)buf * ASB;
        const uint32_t uv = uk + 64 * AST * 2;

        // S = Q K^T (single fp16)
        float s[8][4];
#pragma unroll
        for (int i = 0; i < 8; i++)
#pragma unroll
            for (int j = 0; j < 4; j++) s[i][j] = 0.f;
#pragma unroll
        for (int ks = 0; ks < 4; ks++) {
#pragma unroll
            for (int np = 0; np < 2; np++) {
                uint32_t bf[2][4];
#pragma unroll
                for (int q = 0; q < 2; q++) {
                    uint32_t koff = (uint32_t)((((np * 2 + q) * 16 + brow) * AST + ks * 16 + bcol) * 2);
                    LDSM_X4(bf[q][0], bf[q][1], bf[q][2], bf[q][3], uk + koff);
                }
#pragma unroll
                for (int q = 0; q < 2; q++) {
                    mmah(s[4 * np + 2 * q],     qf[ks], bf[q][0], bf[q][1]);
                    mmah(s[4 * np + 2 * q + 1], qf[ks], bf[q][2], bf[q][3]);
                }
            }
        }

        float mx0 = -1e30f, mx8 = -1e30f;
#pragma unroll
        for (int nt = 0; nt < 8; nt++) {
            int kd0 = kdoc[buf][nt * 8 + 2 * t], kd1 = kdoc[buf][nt * 8 + 2 * t + 1];
            s[nt][0] = (qd0 == kd0) ? s[nt][0] * ATT_SCALE : -1e30f;
            s[nt][1] = (qd0 == kd1) ? s[nt][1] * ATT_SCALE : -1e30f;
            s[nt][2] = (qd8 == kd0) ? s[nt][2] * ATT_SCALE : -1e30f;
            s[nt][3] = (qd8 == kd1) ? s[nt][3] * ATT_SCALE : -1e30f;
            mx0 = fmaxf(mx0, fmaxf(s[nt][0], s[nt][1]));
            mx8 = fmaxf(mx8, fmaxf(s[nt][2], s[nt][3]));
        }
        mx0 = fmaxf(mx0, __shfl_xor_sync(0xffffffffu, mx0, 1));
        mx0 = fmaxf(mx0, __shfl_xor_sync(0xffffffffu, mx0, 2));
        mx8 = fmaxf(mx8, __shfl_xor_sync(0xffffffffu, mx8, 1));
        mx8 = fmaxf(mx8, __shfl_xor_sync(0xffffffffu, mx8, 2));
        const float mn0 = fmaxf(m0, mx0), mn8 = fmaxf(m8, mx8);
        const float f0 = __expf(m0 - mn0), f8 = __expf(m8 - mn8);
        float sum0 = 0.f, sum8 = 0.f;
#pragma unroll
        for (int nt = 0; nt < 8; nt++) {
            s[nt][0] = (s[nt][0] > -1e29f) ? __expf(s[nt][0] - mn0) : 0.f;
            s[nt][1] = (s[nt][1] > -1e29f) ? __expf(s[nt][1] - mn0) : 0.f;
            s[nt][2] = (s[nt][2] > -1e29f) ? __expf(s[nt][2] - mn8) : 0.f;
            s[nt][3] = (s[nt][3] > -1e29f) ? __expf(s[nt][3] - mn8) : 0.f;
            sum0 += s[nt][0] + s[nt][1];
            sum8 += s[nt][2] + s[nt][3];
        }
        sum0 += __shfl_xor_sync(0xffffffffu, sum0, 1);
        sum0 += __shfl_xor_sync(0xffffffffu, sum0, 2);
        sum8 += __shfl_xor_sync(0xffffffffu, sum8, 1);
        sum8 += __shfl_xor_sync(0xffffffffu, sum8, 2);
        l0 = l0 * f0 + sum0;  l8 = l8 * f8 + sum8;
        m0 = mn0;             m8 = mn8;
#pragma unroll
        for (int nt = 0; nt < 8; nt++) {
            o[nt][0] *= f0; o[nt][1] *= f0;
            o[nt][2] *= f8; o[nt][3] *= f8;
        }

        // O += P V (single fp16)
#pragma unroll
        for (int ks = 0; ks < 4; ks++) {
            uint32_t pa[4];
            pa[0] = packh(s[2 * ks][0],     s[2 * ks][1]);
            pa[1] = packh(s[2 * ks][2],     s[2 * ks][3]);
            pa[2] = packh(s[2 * ks + 1][0], s[2 * ks + 1][1]);
            pa[3] = packh(s[2 * ks + 1][2], s[2 * ks + 1][3]);
            uint32_t rowoff = (uint32_t)(ks * 16 * AST * 2) + lmoff;
#pragma unroll
            for (int dp = 0; dp < 2; dp++) {
                uint32_t vf[2][4];
#pragma unroll
                for (int q = 0; q < 2; q++) {
                    uint32_t addr = rowoff + (uint32_t)((dp * 2 + q) * 16 * 2);
                    LDSM_X4_T(vf[q][0], vf[q][1], vf[q][2], vf[q][3], uv + addr);
                }
#pragma unroll
                for (int q = 0; q < 2; q++) {
                    mmah(o[4 * dp + 2 * q],     pa, vf[q][0], vf[q][1]);
                    mmah(o[4 * dp + 2 * q + 1], pa, vf[q][2], vf[q][3]);
                }
            }
        }
        __syncthreads();
    }

    const float inv0 = 1.f / l0, inv8 = 1.f / l8;
    const size_t ob0 = rowbase + (size_t)(wrow + g) * Dn;
    const size_t ob8 = rowbase + (size_t)(wrow + g + 8) * Dn;
#pragma unroll
    for (int nt = 0; nt < 8; nt++) {
        int c = nt * 8 + 2 * t;
        *(uint32_t*)&ao[ob0 + c] = packh(o[nt][0] * inv0, o[nt][1] * inv0);
        *(uint32_t*)&ao[ob8 + c] = packh(o[nt][2] * inv8, o[nt][3] * inv8);
    }
}

// ---------------------------------------------------------------------------
extern "C" void kernel_launch(void* const* d_in, const int* in_sizes, int n_in,
                              void* d_out, int out_size)
{
    (void)in_sizes; (void)n_in; (void)out_size;
    const float* x  = (const float*)d_in[0];
    const float* wq = (const float*)d_in[1];
    const float* bq = (const float*)d_in[2];
    const float* wk = (const float*)d_in[3];
    const float* bk = (const float*)d_in[4];
    const float* wv = (const float*)d_in[5];
    const float* bv = (const float*)d_in[6];
    const float* wo = (const float*)d_in[7];
    const float* bo = (const float*)d_in[8];
    const int*  doc = (const int*)d_in[9];
    float* out = (float*)d_out;

    __half *xh, *wqh, *wkh, *wvh, *woh, *qh, *kh, *vh, *aoh;
    int* dr;
    cudaGetSymbolAddress((void**)&xh, g_xh);
    cudaGetSymbolAddress((void**)&wqh, g_wqh);
    cudaGetSymbolAddress((void**)&wkh, g_wkh);
    cudaGetSymbolAddress((void**)&wvh, g_wvh);
    cudaGetSymbolAddress((void**)&woh, g_woh);
    cudaGetSymbolAddress((void**)&qh, g_qh);
    cudaGetSymbolAddress((void**)&kh, g_kh);
    cudaGetSymbolAddress((void**)&vh, g_vh);
    cudaGetSymbolAddress((void**)&aoh, g_aoh);
    cudaGetSymbolAddress((void**)&dr, g_docrange);

    const int nX4 = Mn * Dn / 4, nW4 = Dn * Dn / 4;
    cvt_f16<<<(nX4 + 255) / 256, 256>>>((const float4*)x, (__half2*)xh, nX4);
    dim3 gw((nW4 + 255) / 256, 4);
    cvt_w4<<<gw, 256>>>((const float4*)wq, (const float4*)wk,
        (const float4*)wv, (const float4*)wo,
        (__half2*)wqh, (__half2*)wkh, (__half2*)wvh, (__half2*)woh, nW4);
    range_init<<<1, 32>>>(dr);
    range_scan<<<Sn / 256, 256>>>(doc, dr);

    const int gemm_smem = 4 * STAGE * (int)sizeof(__half);  // 40960
    cudaFuncSetAttribute(gemm_f16, cudaFuncAttributeMaxDynamicSharedMemorySize, gemm_smem);

    // fused QKV (fp16 out)
    dim3 ggq(24, Mn / 128);
    gemm_f16<<<ggq, 256, gemm_smem>>>(xh,
        wqh, wkh, wvh, bq, bk, bv,
        nullptr, qh, kh, vh, Mn, Dn, Dn);

    const int attn_smem = 2 * ASB;   // 36864
    cudaFuncSetAttribute(attn_f16, cudaFuncAttributeMaxDynamicSharedMemorySize, attn_smem);
    dim3 ga(Sn / 64, Hn, Bn);
    attn_f16<<<ga, 128, attn_smem>>>(qh, kh, vh, doc, dr, aoh);

    // O projection (fp32 out)
    dim3 ggo(8, Mn / 128);
    gemm_f16<<<ggo, 256, gemm_smem>>>(aoh,
        woh, woh, woh, bo, bo, bo,
        out, nullptr, nullptr, nullptr, Mn, Dn, Dn);
}